// round 15
// baseline (speedup 1.0000x reference)
#include <cuda_runtime.h>
#include <cuda_fp16.h>
#include <cstdint>

#define BL   (4 * 4096)   // B*L tokens
#define DIM  1024
#define HEADS 16
#define HD    64

#define BM 128
#define BN 256
#define KT_ELEMS 64                 // K-tile: 64 halves = 128 B rows
#define NT (DIM / KT_ELEMS)         // 16 K-tiles
#define NSTAGE 3
#define LDK 72                      // padded row (halves): conflict-free ldsm
#define A_STAGE (128 * LDK)         // halves
#define B_STAGE (256 * LDK)
#define SMEM_BYTES (NSTAGE * (A_STAGE + B_STAGE) * 2)   // 165,888 B

// Static scratch (allowed): fp16 projections + fp16 operand copies.
__device__ __half g_qkv[3][(size_t)BL * DIM];
__device__ __half g_xh[(size_t)BL * DIM];
__device__ __half g_wh[3][(size_t)DIM * DIM];

// ---------------- helpers ----------------
__device__ __forceinline__ uint32_t s2u(const void* p) {
    return (uint32_t)__cvta_generic_to_shared(p);
}
__device__ __forceinline__ void cp16(uint32_t sdst, const void* g) {
    asm volatile("cp.async.cg.shared.global [%0], [%1], 16;" :: "r"(sdst), "l"(g));
}
__device__ __forceinline__ uint32_t packh2(float lo, float hi) {
    uint32_t r;
    asm("cvt.rn.f16x2.f32 %0, %1, %2;" : "=r"(r) : "f"(hi), "f"(lo));
    return r;
}
__device__ __forceinline__ float2 unpackh2(uint32_t v) {
    __half2 h = *(__half2*)&v;
    return make_float2(__half2float(__low2half(h)), __half2float(__high2half(h)));
}
__device__ __forceinline__ void ldsm_x4(uint32_t* r, uint32_t addr) {
    asm volatile("ldmatrix.sync.aligned.m8n8.x4.shared.b16 {%0,%1,%2,%3}, [%4];"
        : "=r"(r[0]), "=r"(r[1]), "=r"(r[2]), "=r"(r[3]) : "r"(addr));
}
__device__ __forceinline__ void mma_f16(float* d,
    uint32_t a0, uint32_t a1, uint32_t a2, uint32_t a3,
    uint32_t b0, uint32_t b1)
{
    asm volatile(
        "mma.sync.aligned.m16n8k16.row.col.f32.f16.f16.f32 "
        "{%0,%1,%2,%3}, {%4,%5,%6,%7}, {%8,%9}, {%0,%1,%2,%3};"
        : "+f"(d[0]), "+f"(d[1]), "+f"(d[2]), "+f"(d[3])
        : "r"(a0), "r"(a1), "r"(a2), "r"(a3), "r"(b0), "r"(b1));
}

// ---------------- pre-pass: round operands to fp16 ----------------
__global__ __launch_bounds__(256) void conv_fp16(
    const float4* __restrict__ X, const float4* __restrict__ Wq,
    const float4* __restrict__ Wk, const float4* __restrict__ Wv)
{
    const int NX8 = BL * DIM / 8;
    const int NW8 = DIM * DIM / 8;
    const int stride = gridDim.x * blockDim.x;

    auto pack8 = [](float4 v0, float4 v1) {
        uint4 o;
        o.x = packh2(v0.x, v0.y);
        o.y = packh2(v0.z, v0.w);
        o.z = packh2(v1.x, v1.y);
        o.w = packh2(v1.z, v1.w);
        return o;
    };

    uint4* xh = (uint4*)g_xh;
    for (int k = blockIdx.x * blockDim.x + threadIdx.x; k < NX8; k += stride)
        xh[k] = pack8(X[2 * k], X[2 * k + 1]);
    for (int k = blockIdx.x * blockDim.x + threadIdx.x; k < NW8; k += stride) {
        ((uint4*)g_wh[0])[k] = pack8(Wq[2 * k], Wq[2 * k + 1]);
        ((uint4*)g_wh[1])[k] = pack8(Wk[2 * k], Wk[2 * k + 1]);
        ((uint4*)g_wh[2])[k] = pack8(Wv[2 * k], Wv[2 * k + 1]);
    }
}

// ---------------- fp16 mma.sync GEMM (epilogue now writes fp16) ----------------
__global__ __launch_bounds__(256, 1) void qkv_gemm()
{
    extern __shared__ __half smem[];
    __half* As = smem;                      // [NSTAGE][128][LDK]
    __half* Bs = smem + NSTAGE * A_STAGE;   // [NSTAGE][256][LDK]

    const int z = blockIdx.z;
    const __half* X = g_xh;
    const __half* W = g_wh[z];
    __half* C = g_qkv[z];

    const int bm = blockIdx.y * BM;
    const int bn = blockIdx.x * BN;

    const int tid  = threadIdx.x;
    const int warp = tid >> 5;
    const int lane = tid & 31;
    const int wm = (warp & 1) * 64;
    const int wn = (warp >> 1) * 64;
    const int g  = lane >> 2;
    const int t  = lane & 3;

    const int aRow = (lane & 7) + (lane & 8);
    const int aK   = (lane & 16) >> 1;
    const int bCol = (lane & 7) + ((lane & 16) >> 1);
    const int bK   = (lane & 8);

    float acc[4][8][4];
    #pragma unroll
    for (int i = 0; i < 4; i++)
        #pragma unroll
        for (int j = 0; j < 8; j++)
            #pragma unroll
            for (int k = 0; k < 4; k++) acc[i][j][k] = 0.f;

    auto load_tile = [&](int s, int kt) {
        const int k0 = kt * KT_ELEMS;
        __half* Ad = As + s * A_STAGE;
        __half* Bd = Bs + s * B_STAGE;
        #pragma unroll
        for (int i = 0; i < 4; i++) {
            int ch = tid + i * 256;
            int r = ch >> 3, c = ch & 7;
            cp16(s2u(Ad + r * LDK + c * 8), X + (size_t)(bm + r) * DIM + k0 + c * 8);
        }
        #pragma unroll
        for (int i = 0; i < 8; i++) {
            int ch = tid + i * 256;
            int r = ch >> 3, c = ch & 7;
            cp16(s2u(Bd + r * LDK + c * 8), W + (size_t)(bn + r) * DIM + k0 + c * 8);
        }
        asm volatile("cp.async.commit_group;");
    };

    load_tile(0, 0);
    load_tile(1, 1);

    for (int kt = 0; kt < NT; kt++) {
        if (kt < NT - 1) asm volatile("cp.async.wait_group 1;");
        else             asm volatile("cp.async.wait_group 0;");
        __syncthreads();

        const int s = kt % 3;
        const uint32_t aBase = s2u(As + s * A_STAGE) + ((wm + aRow) * LDK + aK) * 2;
        const uint32_t bBase = s2u(Bs + s * B_STAGE) + ((wn + bCol) * LDK + bK) * 2;

        #pragma unroll
        for (int ks = 0; ks < 4; ks++) {
            uint32_t a[4][4], b[4][4];
            #pragma unroll
            for (int mt = 0; mt < 4; mt++)
                ldsm_x4(a[mt], aBase + (mt * 16 * LDK + ks * 16) * 2);
            #pragma unroll
            for (int j = 0; j < 4; j++)
                ldsm_x4(b[j], bBase + (j * 16 * LDK + ks * 16) * 2);
            #pragma unroll
            for (int mt = 0; mt < 4; mt++)
                #pragma unroll
                for (int j = 0; j < 4; j++) {
                    mma_f16(acc[mt][2 * j],
                            a[mt][0], a[mt][1], a[mt][2], a[mt][3],
                            b[j][0], b[j][1]);
                    mma_f16(acc[mt][2 * j + 1],
                            a[mt][0], a[mt][1], a[mt][2], a[mt][3],
                            b[j][2], b[j][3]);
                }
        }
        if (kt + 2 < NT) load_tile((kt + 2) % 3, kt + 2);
    }

    // fp16 epilogue: each acc quad covers rows (g, g+8), cols (t*2, t*2+1).
    #pragma unroll
    for (int mt = 0; mt < 4; mt++) {
        #pragma unroll
        for (int nt = 0; nt < 8; nt++) {
            int row = bm + wm + mt * 16 + g;
            int col = bn + wn + nt * 8 + t * 2;
            *(uint32_t*)&C[(size_t)row * DIM + col] =
                packh2(acc[mt][nt][0], acc[mt][nt][1]);
            *(uint32_t*)&C[(size_t)(row + 8) * DIM + col] =
                packh2(acc[mt][nt][2], acc[mt][nt][3]);
        }
    }
}

// ---------------- fused per-token attention (fp16 inputs, fp32 math) ----------------
#define TPB 2
__global__ __launch_bounds__(128 * TPB) void attn(float* __restrict__ out)
{
    __shared__ __align__(16) float sQ[TPB][HEADS][68];
    __shared__ __align__(16) float sK[TPB][HEADS][68];
    __shared__ __align__(16) float sV[TPB][HEADS][HD];
    __shared__ __align__(16) float sM[TPB][HEADS][20];

    const int tk  = threadIdx.x >> 7;       // token slot in block
    const int t   = threadIdx.x & 127;      // thread within token
    const int tok = blockIdx.x * TPB + tk;

    const uint4* Qp = (const uint4*)(g_qkv[0] + (size_t)tok * DIM);
    const uint4* Kp = (const uint4*)(g_qkv[1] + (size_t)tok * DIM);
    const uint4* Vp = (const uint4*)(g_qkv[2] + (size_t)tok * DIM);

    // 1024 halves per matrix = 128 uint4 loads; exactly 1 per thread each.
    {
        const int h = t >> 3;
        const int d = (t & 7) * 8;
        uint4 qv = Qp[t], kv = Kp[t], vv = Vp[t];
        float2 a, b;
        a = unpackh2(qv.x); b = unpackh2(qv.y);
        *(float4*)&sQ[tk][h][d]     = make_float4(a.x, a.y, b.x, b.y);
        a = unpackh2(qv.z); b = unpackh2(qv.w);
        *(float4*)&sQ[tk][h][d + 4] = make_float4(a.x, a.y, b.x, b.y);
        a = unpackh2(kv.x); b = unpackh2(kv.y);
        *(float4*)&sK[tk][h][d]     = make_float4(a.x, a.y, b.x, b.y);
        a = unpackh2(kv.z); b = unpackh2(kv.w);
        *(float4*)&sK[tk][h][d + 4] = make_float4(a.x, a.y, b.x, b.y);
        a = unpackh2(vv.x); b = unpackh2(vv.y);
        *(float4*)&sV[tk][h][d]     = make_float4(a.x, a.y, b.x, b.y);
        a = unpackh2(vv.z); b = unpackh2(vv.w);
        *(float4*)&sV[tk][h][d + 4] = make_float4(a.x, a.y, b.x, b.y);
    }
    __syncthreads();

    if (t < 64) {
        // K softmax over heads, one column d per thread.
        const int d = t;
        float v[HEADS], mx = -1e30f;
        #pragma unroll
        for (int h = 0; h < HEADS; h++) { v[h] = sK[tk][h][d]; mx = fmaxf(mx, v[h]); }
        float s = 0.f;
        #pragma unroll
        for (int h = 0; h < HEADS; h++) { v[h] = __expf(v[h] - mx); s += v[h]; }
        const float r = 1.f / s;
        #pragma unroll
        for (int h = 0; h < HEADS; h++) sK[tk][h][d] = v[h] * r;
    } else {
        // Q softmax over head_dim: 4 lanes per row, shfl quad-reduce.
        const int h = (t - 64) >> 2;
        const int q = t & 3;
        float4 v0 = *(float4*)&sQ[tk][h][q * 16];
        float4 v1 = *(float4*)&sQ[tk][h][q * 16 + 4];
        float4 v2 = *(float4*)&sQ[tk][h][q * 16 + 8];
        float4 v3 = *(float4*)&sQ[tk][h][q * 16 + 12];
        float mx = fmaxf(fmaxf(fmaxf(v0.x, v0.y), fmaxf(v0.z, v0.w)),
                         fmaxf(fmaxf(v1.x, v1.y), fmaxf(v1.z, v1.w)));
        mx = fmaxf(mx, fmaxf(fmaxf(fmaxf(v2.x, v2.y), fmaxf(v2.z, v2.w)),
                             fmaxf(fmaxf(v3.x, v3.y), fmaxf(v3.z, v3.w))));
        mx = fmaxf(mx, __shfl_xor_sync(0xFFFFFFFF, mx, 1));
        mx = fmaxf(mx, __shfl_xor_sync(0xFFFFFFFF, mx, 2));
        v0.x = __expf(v0.x - mx); v0.y = __expf(v0.y - mx);
        v0.z = __expf(v0.z - mx); v0.w = __expf(v0.w - mx);
        v1.x = __expf(v1.x - mx); v1.y = __expf(v1.y - mx);
        v1.z = __expf(v1.z - mx); v1.w = __expf(v1.w - mx);
        v2.x = __expf(v2.x - mx); v2.y = __expf(v2.y - mx);
        v2.z = __expf(v2.z - mx); v2.w = __expf(v2.w - mx);
        v3.x = __expf(v3.x - mx); v3.y = __expf(v3.y - mx);
        v3.z = __expf(v3.z - mx); v3.w = __expf(v3.w - mx);
        float s = v0.x + v0.y + v0.z + v0.w + v1.x + v1.y + v1.z + v1.w
                + v2.x + v2.y + v2.z + v2.w + v3.x + v3.y + v3.z + v3.w;
        s += __shfl_xor_sync(0xFFFFFFFF, s, 1);
        s += __shfl_xor_sync(0xFFFFFFFF, s, 2);
        const float r = 1.f / s;
        v0.x *= r; v0.y *= r; v0.z *= r; v0.w *= r;
        v1.x *= r; v1.y *= r; v1.z *= r; v1.w *= r;
        v2.x *= r; v2.y *= r; v2.z *= r; v2.w *= r;
        v3.x *= r; v3.y *= r; v3.z *= r; v3.w *= r;
        *(float4*)&sQ[tk][h][q * 16]      = v0;
        *(float4*)&sQ[tk][h][q * 16 + 4]  = v1;
        *(float4*)&sQ[tk][h][q * 16 + 8]  = v2;
        *(float4*)&sQ[tk][h][q * 16 + 12] = v3;
    }
    __syncthreads();

    // M(16x16) = sQ @ sK^T via float4 row-dots: 2x2 tile per thread (64 thr).
    if (t < 64) {
        const int i0 = (t >> 3) * 2;
        const int j0 = (t & 7) * 2;
        float m00 = 0.f, m01 = 0.f, m10 = 0.f, m11 = 0.f;
        #pragma unroll
        for (int d4 = 0; d4 < 16; d4++) {
            const float4 q0 = *(const float4*)&sQ[tk][i0    ][d4 * 4];
            const float4 q1 = *(const float4*)&sQ[tk][i0 + 1][d4 * 4];
            const float4 k0 = *(const float4*)&sK[tk][j0    ][d4 * 4];
            const float4 k1 = *(const float4*)&sK[tk][j0 + 1][d4 * 4];
            m00 += q0.x * k0.x + q0.y * k0.y + q0.z * k0.z + q0.w * k0.w;
            m01 += q0.x * k1.x + q0.y * k1.y + q0.z * k1.z + q0.w * k1.w;
            m10 += q1.x * k0.x + q1.y * k0.y + q1.z * k0.z + q1.w * k0.w;
            m11 += q1.x * k1.x + q1.y * k1.y + q1.z * k1.z + q1.w * k1.w;
        }
        sM[tk][i0    ][j0]     = m00; sM[tk][i0    ][j0 + 1] = m01;
        sM[tk][i0 + 1][j0]     = m10; sM[tk][i0 + 1][j0 + 1] = m11;
    }
    __syncthreads();

    // out(16x64) = M @ V; sM row prefetched into registers.
    const int h  = t >> 3;
    const int e0 = (t & 7) * 8;
    float4 m0 = *(const float4*)&sM[tk][h][0];
    float4 m1 = *(const float4*)&sM[tk][h][4];
    float4 m2 = *(const float4*)&sM[tk][h][8];
    float4 m3 = *(const float4*)&sM[tk][h][12];
    float m[HEADS] = {m0.x, m0.y, m0.z, m0.w, m1.x, m1.y, m1.z, m1.w,
                      m2.x, m2.y, m2.z, m2.w, m3.x, m3.y, m3.z, m3.w};
    float o[8];
    #pragma unroll
    for (int i = 0; i < 8; i++) o[i] = 0.f;
    #pragma unroll
    for (int k = 0; k < HEADS; k++) {
        const float4 v0 = *(const float4*)&sV[tk][k][e0];
        const float4 v1 = *(const float4*)&sV[tk][k][e0 + 4];
        o[0] += m[k] * v0.x; o[1] += m[k] * v0.y;
        o[2] += m[k] * v0.z; o[3] += m[k] * v0.w;
        o[4] += m[k] * v1.x; o[5] += m[k] * v1.y;
        o[6] += m[k] * v1.z; o[7] += m[k] * v1.w;
    }
    float* O = out + (size_t)tok * DIM + t * 8;   // h*64 + e0 == t*8
    *(float4*)O       = make_float4(o[0], o[1], o[2], o[3]);
    *(float4*)(O + 4) = make_float4(o[4], o[5], o[6], o[7]);
}

extern "C" void kernel_launch(void* const* d_in, const int* in_sizes, int n_in,
                              void* d_out, int out_size)
{
    const float4* X  = (const float4*)d_in[0];
    const float4* Wq = (const float4*)d_in[1];
    const float4* Wk = (const float4*)d_in[2];
    const float4* Wv = (const float4*)d_in[3];
    float* out = (float*)d_out;

    cudaFuncSetAttribute(qkv_gemm,
                         cudaFuncAttributeMaxDynamicSharedMemorySize, SMEM_BYTES);

    conv_fp16<<<2048, 256>>>(X, Wq, Wk, Wv);

    dim3 grid_gemm(DIM / BN, BL / BM, 3);   // (4, 128, 3)
    qkv_gemm<<<grid_gemm, 256, SMEM_BYTES>>>();

    attn<<<BL / TPB, 128 * TPB>>>(out);
}

// round 16
// speedup vs baseline: 1.0011x; 1.0011x over previous
#include <cuda_runtime.h>
#include <cuda_fp16.h>
#include <cstdint>

#define BL   (4 * 4096)   // B*L tokens
#define DIM  1024
#define HEADS 16
#define HD    64

#define BM 128
#define BN 256
#define KT_ELEMS 64                 // K-tile: 64 halves = 128 B rows
#define NT (DIM / KT_ELEMS)         // 16 K-tiles
#define NSTAGE 3
#define LDK 72                      // padded row (halves): conflict-free ldsm
#define A_STAGE (128 * LDK)         // halves
#define B_STAGE (256 * LDK)
#define SMEM_BYTES (NSTAGE * (A_STAGE + B_STAGE) * 2)   // 165,888 B

// Static scratch (allowed): fp16 projections + fp16 operand copies.
__device__ __half g_qkv[3][(size_t)BL * DIM];
__device__ __half g_xh[(size_t)BL * DIM];
__device__ __half g_wh[3][(size_t)DIM * DIM];

// ---------------- helpers ----------------
__device__ __forceinline__ uint32_t s2u(const void* p) {
    return (uint32_t)__cvta_generic_to_shared(p);
}
__device__ __forceinline__ void cp16(uint32_t sdst, const void* g) {
    asm volatile("cp.async.cg.shared.global [%0], [%1], 16;" :: "r"(sdst), "l"(g));
}
__device__ __forceinline__ uint32_t packh2(float lo, float hi) {
    uint32_t r;
    asm("cvt.rn.f16x2.f32 %0, %1, %2;" : "=r"(r) : "f"(hi), "f"(lo));
    return r;
}
__device__ __forceinline__ float2 unpackh2(uint32_t v) {
    __half2 h = *(__half2*)&v;
    return make_float2(__half2float(__low2half(h)), __half2float(__high2half(h)));
}
__device__ __forceinline__ void ldsm_x4(uint32_t* r, uint32_t addr) {
    asm volatile("ldmatrix.sync.aligned.m8n8.x4.shared.b16 {%0,%1,%2,%3}, [%4];"
        : "=r"(r[0]), "=r"(r[1]), "=r"(r[2]), "=r"(r[3]) : "r"(addr));
}
__device__ __forceinline__ void mma_f16(float* d,
    uint32_t a0, uint32_t a1, uint32_t a2, uint32_t a3,
    uint32_t b0, uint32_t b1)
{
    asm volatile(
        "mma.sync.aligned.m16n8k16.row.col.f32.f16.f16.f32 "
        "{%0,%1,%2,%3}, {%4,%5,%6,%7}, {%8,%9}, {%0,%1,%2,%3};"
        : "+f"(d[0]), "+f"(d[1]), "+f"(d[2]), "+f"(d[3])
        : "r"(a0), "r"(a1), "r"(a2), "r"(a3), "r"(b0), "r"(b1));
}

// ---------------- pre-pass: round operands to fp16 ----------------
__global__ __launch_bounds__(256) void conv_fp16(
    const float4* __restrict__ X, const float4* __restrict__ Wq,
    const float4* __restrict__ Wk, const float4* __restrict__ Wv)
{
    const int NX8 = BL * DIM / 8;
    const int NW8 = DIM * DIM / 8;
    const int stride = gridDim.x * blockDim.x;

    auto pack8 = [](float4 v0, float4 v1) {
        uint4 o;
        o.x = packh2(v0.x, v0.y);
        o.y = packh2(v0.z, v0.w);
        o.z = packh2(v1.x, v1.y);
        o.w = packh2(v1.z, v1.w);
        return o;
    };

    uint4* xh = (uint4*)g_xh;
    for (int k = blockIdx.x * blockDim.x + threadIdx.x; k < NX8; k += stride)
        xh[k] = pack8(X[2 * k], X[2 * k + 1]);
    for (int k = blockIdx.x * blockDim.x + threadIdx.x; k < NW8; k += stride) {
        ((uint4*)g_wh[0])[k] = pack8(Wq[2 * k], Wq[2 * k + 1]);
        ((uint4*)g_wh[1])[k] = pack8(Wk[2 * k], Wk[2 * k + 1]);
        ((uint4*)g_wh[2])[k] = pack8(Wv[2 * k], Wv[2 * k + 1]);
    }
}

// ---------------- fp16 mma.sync GEMM (epilogue now writes fp16) ----------------
__global__ __launch_bounds__(256, 1) void qkv_gemm()
{
    extern __shared__ __half smem[];
    __half* As = smem;                      // [NSTAGE][128][LDK]
    __half* Bs = smem + NSTAGE * A_STAGE;   // [NSTAGE][256][LDK]

    const int z = blockIdx.z;
    const __half* X = g_xh;
    const __half* W = g_wh[z];
    __half* C = g_qkv[z];

    const int bm = blockIdx.y * BM;
    const int bn = blockIdx.x * BN;

    const int tid  = threadIdx.x;
    const int warp = tid >> 5;
    const int lane = tid & 31;
    const int wm = (warp & 1) * 64;
    const int wn = (warp >> 1) * 64;
    const int g  = lane >> 2;
    const int t  = lane & 3;

    const int aRow = (lane & 7) + (lane & 8);
    const int aK   = (lane & 16) >> 1;
    const int bCol = (lane & 7) + ((lane & 16) >> 1);
    const int bK   = (lane & 8);

    float acc[4][8][4];
    #pragma unroll
    for (int i = 0; i < 4; i++)
        #pragma unroll
        for (int j = 0; j < 8; j++)
            #pragma unroll
            for (int k = 0; k < 4; k++) acc[i][j][k] = 0.f;

    auto load_tile = [&](int s, int kt) {
        const int k0 = kt * KT_ELEMS;
        __half* Ad = As + s * A_STAGE;
        __half* Bd = Bs + s * B_STAGE;
        #pragma unroll
        for (int i = 0; i < 4; i++) {
            int ch = tid + i * 256;
            int r = ch >> 3, c = ch & 7;
            cp16(s2u(Ad + r * LDK + c * 8), X + (size_t)(bm + r) * DIM + k0 + c * 8);
        }
        #pragma unroll
        for (int i = 0; i < 8; i++) {
            int ch = tid + i * 256;
            int r = ch >> 3, c = ch & 7;
            cp16(s2u(Bd + r * LDK + c * 8), W + (size_t)(bn + r) * DIM + k0 + c * 8);
        }
        asm volatile("cp.async.commit_group;");
    };

    load_tile(0, 0);
    load_tile(1, 1);

    for (int kt = 0; kt < NT; kt++) {
        if (kt < NT - 1) asm volatile("cp.async.wait_group 1;");
        else             asm volatile("cp.async.wait_group 0;");
        __syncthreads();

        const int s = kt % 3;
        const uint32_t aBase = s2u(As + s * A_STAGE) + ((wm + aRow) * LDK + aK) * 2;
        const uint32_t bBase = s2u(Bs + s * B_STAGE) + ((wn + bCol) * LDK + bK) * 2;

        #pragma unroll
        for (int ks = 0; ks < 4; ks++) {
            uint32_t a[4][4], b[4][4];
            #pragma unroll
            for (int mt = 0; mt < 4; mt++)
                ldsm_x4(a[mt], aBase + (mt * 16 * LDK + ks * 16) * 2);
            #pragma unroll
            for (int j = 0; j < 4; j++)
                ldsm_x4(b[j], bBase + (j * 16 * LDK + ks * 16) * 2);
            #pragma unroll
            for (int mt = 0; mt < 4; mt++)
                #pragma unroll
                for (int j = 0; j < 4; j++) {
                    mma_f16(acc[mt][2 * j],
                            a[mt][0], a[mt][1], a[mt][2], a[mt][3],
                            b[j][0], b[j][1]);
                    mma_f16(acc[mt][2 * j + 1],
                            a[mt][0], a[mt][1], a[mt][2], a[mt][3],
                            b[j][2], b[j][3]);
                }
        }
        if (kt + 2 < NT) load_tile((kt + 2) % 3, kt + 2);
    }

    // fp16 epilogue: each acc quad covers rows (g, g+8), cols (t*2, t*2+1).
    #pragma unroll
    for (int mt = 0; mt < 4; mt++) {
        #pragma unroll
        for (int nt = 0; nt < 8; nt++) {
            int row = bm + wm + mt * 16 + g;
            int col = bn + wn + nt * 8 + t * 2;
            *(uint32_t*)&C[(size_t)row * DIM + col] =
                packh2(acc[mt][nt][0], acc[mt][nt][1]);
            *(uint32_t*)&C[(size_t)(row + 8) * DIM + col] =
                packh2(acc[mt][nt][2], acc[mt][nt][3]);
        }
    }
}

// ---------------- fused per-token attention (fp16 inputs, fp32 math) ----------------
#define TPB 2
__global__ __launch_bounds__(128 * TPB) void attn(float* __restrict__ out)
{
    __shared__ __align__(16) float sQ[TPB][HEADS][68];
    __shared__ __align__(16) float sK[TPB][HEADS][68];
    __shared__ __align__(16) float sV[TPB][HEADS][HD];
    __shared__ __align__(16) float sM[TPB][HEADS][20];

    const int tk  = threadIdx.x >> 7;       // token slot in block
    const int t   = threadIdx.x & 127;      // thread within token
    const int tok = blockIdx.x * TPB + tk;

    const uint4* Qp = (const uint4*)(g_qkv[0] + (size_t)tok * DIM);
    const uint4* Kp = (const uint4*)(g_qkv[1] + (size_t)tok * DIM);
    const uint4* Vp = (const uint4*)(g_qkv[2] + (size_t)tok * DIM);

    // 1024 halves per matrix = 128 uint4 loads; exactly 1 per thread each.
    {
        const int h = t >> 3;
        const int d = (t & 7) * 8;
        uint4 qv = Qp[t], kv = Kp[t], vv = Vp[t];
        float2 a, b;
        a = unpackh2(qv.x); b = unpackh2(qv.y);
        *(float4*)&sQ[tk][h][d]     = make_float4(a.x, a.y, b.x, b.y);
        a = unpackh2(qv.z); b = unpackh2(qv.w);
        *(float4*)&sQ[tk][h][d + 4] = make_float4(a.x, a.y, b.x, b.y);
        a = unpackh2(kv.x); b = unpackh2(kv.y);
        *(float4*)&sK[tk][h][d]     = make_float4(a.x, a.y, b.x, b.y);
        a = unpackh2(kv.z); b = unpackh2(kv.w);
        *(float4*)&sK[tk][h][d + 4] = make_float4(a.x, a.y, b.x, b.y);
        a = unpackh2(vv.x); b = unpackh2(vv.y);
        *(float4*)&sV[tk][h][d]     = make_float4(a.x, a.y, b.x, b.y);
        a = unpackh2(vv.z); b = unpackh2(vv.w);
        *(float4*)&sV[tk][h][d + 4] = make_float4(a.x, a.y, b.x, b.y);
    }
    __syncthreads();

    if (t < 64) {
        // K softmax over heads, one column d per thread.
        const int d = t;
        float v[HEADS], mx = -1e30f;
        #pragma unroll
        for (int h = 0; h < HEADS; h++) { v[h] = sK[tk][h][d]; mx = fmaxf(mx, v[h]); }
        float s = 0.f;
        #pragma unroll
        for (int h = 0; h < HEADS; h++) { v[h] = __expf(v[h] - mx); s += v[h]; }
        const float r = 1.f / s;
        #pragma unroll
        for (int h = 0; h < HEADS; h++) sK[tk][h][d] = v[h] * r;
    } else {
        // Q softmax over head_dim: 4 lanes per row, shfl quad-reduce.
        const int h = (t - 64) >> 2;
        const int q = t & 3;
        float4 v0 = *(float4*)&sQ[tk][h][q * 16];
        float4 v1 = *(float4*)&sQ[tk][h][q * 16 + 4];
        float4 v2 = *(float4*)&sQ[tk][h][q * 16 + 8];
        float4 v3 = *(float4*)&sQ[tk][h][q * 16 + 12];
        float mx = fmaxf(fmaxf(fmaxf(v0.x, v0.y), fmaxf(v0.z, v0.w)),
                         fmaxf(fmaxf(v1.x, v1.y), fmaxf(v1.z, v1.w)));
        mx = fmaxf(mx, fmaxf(fmaxf(fmaxf(v2.x, v2.y), fmaxf(v2.z, v2.w)),
                             fmaxf(fmaxf(v3.x, v3.y), fmaxf(v3.z, v3.w))));
        mx = fmaxf(mx, __shfl_xor_sync(0xFFFFFFFF, mx, 1));
        mx = fmaxf(mx, __shfl_xor_sync(0xFFFFFFFF, mx, 2));
        v0.x = __expf(v0.x - mx); v0.y = __expf(v0.y - mx);
        v0.z = __expf(v0.z - mx); v0.w = __expf(v0.w - mx);
        v1.x = __expf(v1.x - mx); v1.y = __expf(v1.y - mx);
        v1.z = __expf(v1.z - mx); v1.w = __expf(v1.w - mx);
        v2.x = __expf(v2.x - mx); v2.y = __expf(v2.y - mx);
        v2.z = __expf(v2.z - mx); v2.w = __expf(v2.w - mx);
        v3.x = __expf(v3.x - mx); v3.y = __expf(v3.y - mx);
        v3.z = __expf(v3.z - mx); v3.w = __expf(v3.w - mx);
        float s = v0.x + v0.y + v0.z + v0.w + v1.x + v1.y + v1.z + v1.w
                + v2.x + v2.y + v2.z + v2.w + v3.x + v3.y + v3.z + v3.w;
        s += __shfl_xor_sync(0xFFFFFFFF, s, 1);
        s += __shfl_xor_sync(0xFFFFFFFF, s, 2);
        const float r = 1.f / s;
        v0.x *= r; v0.y *= r; v0.z *= r; v0.w *= r;
        v1.x *= r; v1.y *= r; v1.z *= r; v1.w *= r;
        v2.x *= r; v2.y *= r; v2.z *= r; v2.w *= r;
        v3.x *= r; v3.y *= r; v3.z *= r; v3.w *= r;
        *(float4*)&sQ[tk][h][q * 16]      = v0;
        *(float4*)&sQ[tk][h][q * 16 + 4]  = v1;
        *(float4*)&sQ[tk][h][q * 16 + 8]  = v2;
        *(float4*)&sQ[tk][h][q * 16 + 12] = v3;
    }
    __syncthreads();

    // M(16x16) = sQ @ sK^T via float4 row-dots: 2x2 tile per thread (64 thr).
    if (t < 64) {
        const int i0 = (t >> 3) * 2;
        const int j0 = (t & 7) * 2;
        float m00 = 0.f, m01 = 0.f, m10 = 0.f, m11 = 0.f;
        #pragma unroll
        for (int d4 = 0; d4 < 16; d4++) {
            const float4 q0 = *(const float4*)&sQ[tk][i0    ][d4 * 4];
            const float4 q1 = *(const float4*)&sQ[tk][i0 + 1][d4 * 4];
            const float4 k0 = *(const float4*)&sK[tk][j0    ][d4 * 4];
            const float4 k1 = *(const float4*)&sK[tk][j0 + 1][d4 * 4];
            m00 += q0.x * k0.x + q0.y * k0.y + q0.z * k0.z + q0.w * k0.w;
            m01 += q0.x * k1.x + q0.y * k1.y + q0.z * k1.z + q0.w * k1.w;
            m10 += q1.x * k0.x + q1.y * k0.y + q1.z * k0.z + q1.w * k0.w;
            m11 += q1.x * k1.x + q1.y * k1.y + q1.z * k1.z + q1.w * k1.w;
        }
        sM[tk][i0    ][j0]     = m00; sM[tk][i0    ][j0 + 1] = m01;
        sM[tk][i0 + 1][j0]     = m10; sM[tk][i0 + 1][j0 + 1] = m11;
    }
    __syncthreads();

    // out(16x64) = M @ V; sM row prefetched into registers.
    const int h  = t >> 3;
    const int e0 = (t & 7) * 8;
    float4 m0 = *(const float4*)&sM[tk][h][0];
    float4 m1 = *(const float4*)&sM[tk][h][4];
    float4 m2 = *(const float4*)&sM[tk][h][8];
    float4 m3 = *(const float4*)&sM[tk][h][12];
    float m[HEADS] = {m0.x, m0.y, m0.z, m0.w, m1.x, m1.y, m1.z, m1.w,
                      m2.x, m2.y, m2.z, m2.w, m3.x, m3.y, m3.z, m3.w};
    float o[8];
    #pragma unroll
    for (int i = 0; i < 8; i++) o[i] = 0.f;
    #pragma unroll
    for (int k = 0; k < HEADS; k++) {
        const float4 v0 = *(const float4*)&sV[tk][k][e0];
        const float4 v1 = *(const float4*)&sV[tk][k][e0 + 4];
        o[0] += m[k] * v0.x; o[1] += m[k] * v0.y;
        o[2] += m[k] * v0.z; o[3] += m[k] * v0.w;
        o[4] += m[k] * v1.x; o[5] += m[k] * v1.y;
        o[6] += m[k] * v1.z; o[7] += m[k] * v1.w;
    }
    float* O = out + (size_t)tok * DIM + t * 8;   // h*64 + e0 == t*8
    *(float4*)O       = make_float4(o[0], o[1], o[2], o[3]);
    *(float4*)(O + 4) = make_float4(o[4], o[5], o[6], o[7]);
}

extern "C" void kernel_launch(void* const* d_in, const int* in_sizes, int n_in,
                              void* d_out, int out_size)
{
    const float4* X  = (const float4*)d_in[0];
    const float4* Wq = (const float4*)d_in[1];
    const float4* Wk = (const float4*)d_in[2];
    const float4* Wv = (const float4*)d_in[3];
    float* out = (float*)d_out;

    cudaFuncSetAttribute(qkv_gemm,
                         cudaFuncAttributeMaxDynamicSharedMemorySize, SMEM_BYTES);

    conv_fp16<<<2048, 256>>>(X, Wq, Wk, Wv);

    dim3 grid_gemm(DIM / BN, BL / BM, 3);   // (4, 128, 3)
    qkv_gemm<<<grid_gemm, 256, SMEM_BYTES>>>();

    attn<<<BL / TPB, 128 * TPB>>>(out);
}